// round 1
// baseline (speedup 1.0000x reference)
#include <cuda_runtime.h>
#include <math.h>

#define NK   10000   // number of rocket kernels
#define SEQ  512
#define NB   8       // batch
#define XS_POS 1536  // smem positions: index = s + 512, s in [-512, 1024)
#define WPB  8       // warps per block (one conv-kernel per warp)
#define NT   256

// Inner accumulation over t for a compile-time tap count K.
// p points at xs[(512 - pad + t0)*8 + b]; each tap j reads p[j*step], step = dil*8.
// Addresses are conflict-free across the warp by construction (Tc odd).
template<int K>
__device__ __forceinline__ void accum_loop(const float* __restrict__ p, int n, int step,
                                           const float* w, float bias,
                                           float& m, float& cnt) {
    for (int t = 0; t < n; ++t) {
        float acc = 0.f;
        #pragma unroll
        for (int j = 0; j < K; ++j)
            acc = fmaf(w[j], p[j * step], acc);
        p += 8;
        float s = acc + bias;
        m = fmaxf(m, s);
        if (s > 0.f) cnt += 1.f;
    }
}

__global__ __launch_bounds__(NT)
void rocket_kernel(const float* __restrict__ x,     // (8,1,512)
                   const float* __restrict__ W,     // (10000,1,11)
                   const float* __restrict__ Bias,  // (10000,)
                   const int*   __restrict__ dil_,  // (10000,)
                   const int*   __restrict__ lo_,   // (10000,)
                   float*       __restrict__ out)   // (8, 20000) interleaved (max, ppv)
{
    // Zero-padded, batch-interleaved x tile: xs[(s+512)*8 + b]
    __shared__ float xs[XS_POS * NB];   // 49152 B

    const int tid = threadIdx.x;

    // zero fill (vectorized)
    float4* xs4 = reinterpret_cast<float4*>(xs);
    #pragma unroll
    for (int idx = tid; idx < XS_POS * NB / 4; idx += NT)
        xs4[idx] = make_float4(0.f, 0.f, 0.f, 0.f);
    __syncthreads();

    // transpose-load x: xs[(s+512)*8 + b] = x[b*512 + s]
    for (int idx = tid; idx < NB * SEQ; idx += NT) {
        int b = idx >> 9;
        int s = idx & 511;
        xs[(s + 512) * 8 + b] = x[idx];
    }
    __syncthreads();

    const int warp = tid >> 5;
    const int lane = tid & 31;
    const int i = blockIdx.x * WPB + warp;
    if (i >= NK) return;

    const int c = lane >> 3;   // t-chunk 0..3
    const int b = lane & 7;    // batch

    // per-conv-kernel params (warp-uniform loads)
    float w[11];
    const float* wrow = W + i * 11;
    #pragma unroll
    for (int j = 0; j < 11; ++j) w[j] = __ldg(wrow + j);
    const float bias = __ldg(Bias + i);
    const int   dil  = __ldg(dil_ + i);
    const int   lo   = __ldg(lo_ + i);

    // recover tap count from exact-zero weight tail (taps >= k are stored 0.0f)
    int k = 11;
    if (w[9] == 0.f && w[10] == 0.f) k = 9;
    if (w[7] == 0.f && w[8] == 0.f) k = 7;
    // lo = 512 + 2*pad - dil*(k-1)  =>  pad exactly:
    const int pad = (lo - SEQ + dil * (k - 1)) >> 1;

    // odd chunk length => the 4 chunk groups hit 4 distinct bank octets
    const int Tc = ((lo + 3) >> 2) | 1;
    const int t0 = c * Tc;
    const int n  = max(0, min(lo - t0, Tc));

    const float* p = xs + ((t0 + 512 - pad) * 8 + b);
    const int step = dil * 8;

    float m   = -INFINITY;
    float cnt = 0.f;

    if (k == 7)      accum_loop<7 >(p, n, step, w, bias, m, cnt);
    else if (k == 9) accum_loop<9 >(p, n, step, w, bias, m, cnt);
    else             accum_loop<11>(p, n, step, w, bias, m, cnt);

    // combine the 4 t-chunks (lanes b, b+8, b+16, b+24)
    m   = fmaxf(m, __shfl_xor_sync(0xffffffffu, m, 16));
    cnt =       cnt + __shfl_xor_sync(0xffffffffu, cnt, 16);
    m   = fmaxf(m, __shfl_xor_sync(0xffffffffu, m, 8));
    cnt =       cnt + __shfl_xor_sync(0xffffffffu, cnt, 8);

    if (c == 0) {
        float2 r;
        r.x = m;                      // max
        r.y = cnt / (float)lo;        // ppv
        reinterpret_cast<float2*>(out)[b * NK + i] = r;  // out[b, 2i], out[b, 2i+1]
    }
}

extern "C" void kernel_launch(void* const* d_in, const int* in_sizes, int n_in,
                              void* d_out, int out_size) {
    const float* x    = (const float*)d_in[0];  // (8,1,512)
    const float* Wt   = (const float*)d_in[1];  // (10000,1,11)
    const float* Bias = (const float*)d_in[2];  // (10000,)
    // d_in[3] = base (unused: pad recovered from lo/dil/k)
    const int*   dil  = (const int*)d_in[4];
    const int*   lo   = (const int*)d_in[5];
    float* out = (float*)d_out;                 // (8, 20000)

    dim3 grid((NK + WPB - 1) / WPB);            // 1250 blocks
    rocket_kernel<<<grid, NT>>>(x, Wt, Bias, dil, lo, out);
}

// round 2
// speedup vs baseline: 1.0633x; 1.0633x over previous
#include <cuda_runtime.h>
#include <math.h>

#define NK     10000   // number of rocket conv-kernels
#define SEQ    512
#define XS_POS 1536    // smem positions: index = s + 512, s in [-512, 1024)
#define NT     256
#define NBLK   592     // 4 CTAs/SM * 148 SMs, all resident

__device__ int g_ctr;

__global__ void reset_ctr_kernel() { g_ctr = 0; }

// Inner loop for compile-time tap count K.
// idx is a float4 index into xs4; tap j reads xs4[idx + j*step4]; idx += 2 per t
// (one position = 8 floats = 2 float4). Conflict-free: Tc odd => chunk residues
// mod 4 uniform => every LDS.128 is exactly 4 wavefronts.
template<int K>
__device__ __forceinline__ void accum(const float4* __restrict__ xs4, int idx, int n,
                                      int step4, const float* w, float bias,
                                      float4& m, float4& cnt) {
    #pragma unroll 2
    for (int t = 0; t < n; ++t) {
        float ax = bias, ay = bias, az = bias, aw = bias;
        #pragma unroll
        for (int j = 0; j < K; ++j) {
            float4 v = xs4[idx + j * step4];
            ax = fmaf(w[j], v.x, ax);
            ay = fmaf(w[j], v.y, ay);
            az = fmaf(w[j], v.z, az);
            aw = fmaf(w[j], v.w, aw);
        }
        idx += 2;
        m.x = fmaxf(m.x, ax);  if (ax > 0.f) cnt.x += 1.f;
        m.y = fmaxf(m.y, ay);  if (ay > 0.f) cnt.y += 1.f;
        m.z = fmaxf(m.z, az);  if (az > 0.f) cnt.z += 1.f;
        m.w = fmaxf(m.w, aw);  if (aw > 0.f) cnt.w += 1.f;
    }
}

__global__ __launch_bounds__(NT)
void rocket_kernel(const float* __restrict__ x,     // (8,1,512)
                   const float* __restrict__ W,     // (10000,1,11)
                   const float* __restrict__ Bias,  // (10000,)
                   const int*   __restrict__ dil_,  // (10000,)
                   const int*   __restrict__ lo_,   // (10000,)
                   float*       __restrict__ out)   // (8, 20000) interleaved (max, ppv)
{
    // Zero-padded, batch-interleaved x tile: xs[(s+512)*8 + b]  (48 KB, staged ONCE per block)
    __shared__ float xs[XS_POS * 8];
    const float4* xs4 = reinterpret_cast<const float4*>(xs);

    const int tid = threadIdx.x;

    // zero fill
    float4* z4 = reinterpret_cast<float4*>(xs);
    #pragma unroll
    for (int i2 = tid; i2 < XS_POS * 8 / 4; i2 += NT)
        z4[i2] = make_float4(0.f, 0.f, 0.f, 0.f);
    __syncthreads();

    // transpose-load x: xs[(s+512)*8 + b] = x[b*512 + s]
    for (int i2 = tid; i2 < 8 * SEQ; i2 += NT) {
        int b = i2 >> 9;
        int s = i2 & 511;
        xs[(s + 512) * 8 + b] = x[i2];
    }
    __syncthreads();

    const int lane = tid & 31;
    const int c = lane >> 1;   // t-chunk 0..15
    const int h = lane & 1;    // batch half: batches 4h..4h+3

    // dynamic work loop: each warp pulls conv-kernel indices
    while (true) {
        int i;
        if (lane == 0) i = atomicAdd(&g_ctr, 1);
        i = __shfl_sync(0xffffffffu, i, 0);
        if (i >= NK) break;

        // per-conv-kernel params (warp-uniform)
        float w[11];
        const float* wrow = W + i * 11;
        #pragma unroll
        for (int j = 0; j < 11; ++j) w[j] = __ldg(wrow + j);
        const float bias = __ldg(Bias + i);
        const int   dil  = __ldg(dil_ + i);
        const int   lo   = __ldg(lo_ + i);

        // recover tap count from exact-zero weight tail
        int k = 11;
        if (w[9] == 0.f && w[10] == 0.f) k = 9;
        if (w[7] == 0.f && w[8] == 0.f) k = 7;
        // lo = 512 + 2*pad - dil*(k-1)
        const int pad = (lo - SEQ + dil * (k - 1)) >> 1;

        // odd chunk length => residues mod 4 uniform across the 16 chunks
        const int Tc = ((lo + 15) >> 4) | 1;
        const int t0 = c * Tc;
        int n = min(lo - t0, Tc);
        if (n < 0) n = 0;

        const int idx   = (t0 + 512 - pad) * 2 + h;  // float4 index
        const int step4 = dil * 2;

        float4 m   = make_float4(-INFINITY, -INFINITY, -INFINITY, -INFINITY);
        float4 cnt = make_float4(0.f, 0.f, 0.f, 0.f);

        if (k == 7)      accum<7 >(xs4, idx, n, step4, w, bias, m, cnt);
        else if (k == 9) accum<9 >(xs4, idx, n, step4, w, bias, m, cnt);
        else             accum<11>(xs4, idx, n, step4, w, bias, m, cnt);

        // reduce across the 16 t-chunks (xor offsets 2..16 keep h fixed)
        #pragma unroll
        for (int off = 2; off < 32; off <<= 1) {
            m.x = fmaxf(m.x, __shfl_xor_sync(0xffffffffu, m.x, off));
            m.y = fmaxf(m.y, __shfl_xor_sync(0xffffffffu, m.y, off));
            m.z = fmaxf(m.z, __shfl_xor_sync(0xffffffffu, m.z, off));
            m.w = fmaxf(m.w, __shfl_xor_sync(0xffffffffu, m.w, off));
            cnt.x += __shfl_xor_sync(0xffffffffu, cnt.x, off);
            cnt.y += __shfl_xor_sync(0xffffffffu, cnt.y, off);
            cnt.z += __shfl_xor_sync(0xffffffffu, cnt.z, off);
            cnt.w += __shfl_xor_sync(0xffffffffu, cnt.w, off);
        }

        if (c == 0) {
            const float inv_lo = 1.f / (float)lo;
            float2* o2 = reinterpret_cast<float2*>(out);
            o2[(4 * h + 0) * NK + i] = make_float2(m.x, cnt.x * inv_lo);
            o2[(4 * h + 1) * NK + i] = make_float2(m.y, cnt.y * inv_lo);
            o2[(4 * h + 2) * NK + i] = make_float2(m.z, cnt.z * inv_lo);
            o2[(4 * h + 3) * NK + i] = make_float2(m.w, cnt.w * inv_lo);
        }
    }
}

extern "C" void kernel_launch(void* const* d_in, const int* in_sizes, int n_in,
                              void* d_out, int out_size) {
    const float* x    = (const float*)d_in[0];  // (8,1,512)
    const float* Wt   = (const float*)d_in[1];  // (10000,1,11)
    const float* Bias = (const float*)d_in[2];  // (10000,)
    // d_in[3] = base (unused: pad recovered from lo/dil/k)
    const int*   dil  = (const int*)d_in[4];
    const int*   lo   = (const int*)d_in[5];
    float* out = (float*)d_out;                 // (8, 20000)

    reset_ctr_kernel<<<1, 1>>>();
    rocket_kernel<<<NBLK, NT>>>(x, Wt, Bias, dil, lo, out);
}

// round 3
// speedup vs baseline: 1.5319x; 1.4407x over previous
#include <cuda_runtime.h>
#include <math.h>

#define NK     10000
#define SEQ    512
#define XS_POS 1792                      // positions: index = s + 512, covers over-read tail
#define SMEM_BYTES (XS_POS * 8 * 4)      // 57344 B, dynamic shared
#define NT     256
#define NBLK   444                       // 3 CTAs/SM * 148 SMs, all resident

typedef unsigned long long ull;

__device__ int g_ctr;
__global__ void reset_ctr_kernel() { g_ctr = 0; }

static __device__ __forceinline__ ull pack2(float a, float b) {
    ull r; asm("mov.b64 %0, {%1, %2};" : "=l"(r) : "f"(a), "f"(b)); return r;
}
static __device__ __forceinline__ void unpack2(ull v, float& a, float& b) {
    asm("mov.b64 {%0, %1}, %2;" : "=f"(a), "=f"(b) : "l"(v));
}
static __device__ __forceinline__ ull fma2(ull a, ull b, ull c) {
    ull r; asm("fma.rn.f32x2 %0, %1, %2, %3;" : "=l"(r) : "l"(a), "l"(b), "l"(c)); return r;
}

// Process one rocket conv-kernel i with compile-time tap count K.
// Lane layout: c = lane>>1 (16 tile-lanes), h = lane&1 (batch half, 4 batches per float4).
// Tile = 4 chain-consecutive outputs t0, t0+d, t0+2d, t0+3d sharing K+3 loads.
template<int K>
static __device__ __forceinline__ void process_i(
    const ulonglong2* __restrict__ xsu, int i, int c, int h,
    const float* __restrict__ w, float bias, int dil, int lo,
    float* __restrict__ out)
{
    // lo = 512 + 2*pad - dil*(K-1)  =>  pad exactly
    const int pad = (lo - SEQ + dil * (K - 1)) >> 1;

    ull wp[K];
#pragma unroll
    for (int j = 0; j < K; ++j) wp[j] = pack2(w[j], w[j]);
    const ull bias2 = pack2(bias, bias);

    const int d4 = dil << 2;
    const int stripes = (lo + d4 - 1) / d4;       // warp-uniform int div, once per i
    const int ntiles = stripes * dil;
    const float inv_d = 1.0f / (float)dil;
    const int inc = dil * 2;                      // ulonglong2-index step per tap
    const int base0 = (SEQ - pad) * 2 + h;

    float m0 = -INFINITY, m1 = -INFINITY, m2 = -INFINITY, m3 = -INFINITY;
    float c0 = 0.f, c1 = 0.f, c2 = 0.f, c3 = 0.f;

    for (int j = c; j < ntiles; j += 16) {
        // (stripe, off) = (j / dil, j % dil) via float reciprocal + correction
        int stripe = __float2int_rd(__int2float_rn(j) * inv_d);
        int off = j - stripe * dil;
        if (off < 0)           { --stripe; off += dil; }
        else if (off >= dil)   { ++stripe; off -= dil; }
        const int t0 = stripe * d4 + off;
        if (t0 >= lo) continue;

        int idx = base0 + t0 * 2;
        ull aL[4], aH[4];
#pragma unroll
        for (int q = 0; q < 4; ++q) { aL[q] = bias2; aH[q] = bias2; }

#pragma unroll
        for (int v = 0; v < K + 3; ++v) {
            const int ph = idx ^ ((idx >> 3) & 6);     // bank swizzle (within 128B row)
            const ulonglong2 L = xsu[ph];
#pragma unroll
            for (int q = 0; q < 4; ++q) {
                const int jj = v - q;
                if (jj >= 0 && jj < K) {
                    aL[q] = fma2(wp[jj], L.x, aL[q]);
                    aH[q] = fma2(wp[jj], L.y, aH[q]);
                }
            }
            idx += inc;
        }

#pragma unroll
        for (int q = 0; q < 4; ++q) {
            if (t0 + q * dil < lo) {
                float s0, s1, s2, s3;
                unpack2(aL[q], s0, s1);
                unpack2(aH[q], s2, s3);
                m0 = fmaxf(m0, s0); if (s0 > 0.f) c0 += 1.f;
                m1 = fmaxf(m1, s1); if (s1 > 0.f) c1 += 1.f;
                m2 = fmaxf(m2, s2); if (s2 > 0.f) c2 += 1.f;
                m3 = fmaxf(m3, s3); if (s3 > 0.f) c3 += 1.f;
            }
        }
    }

    // reduce across the 16 tile-lanes (xor offsets 2..16 keep h fixed)
#pragma unroll
    for (int off = 2; off < 32; off <<= 1) {
        m0 = fmaxf(m0, __shfl_xor_sync(0xffffffffu, m0, off));
        m1 = fmaxf(m1, __shfl_xor_sync(0xffffffffu, m1, off));
        m2 = fmaxf(m2, __shfl_xor_sync(0xffffffffu, m2, off));
        m3 = fmaxf(m3, __shfl_xor_sync(0xffffffffu, m3, off));
        c0 += __shfl_xor_sync(0xffffffffu, c0, off);
        c1 += __shfl_xor_sync(0xffffffffu, c1, off);
        c2 += __shfl_xor_sync(0xffffffffu, c2, off);
        c3 += __shfl_xor_sync(0xffffffffu, c3, off);
    }

    if (c == 0) {
        const float il = 1.f / (float)lo;
        float2* o2 = reinterpret_cast<float2*>(out);
        o2[(4 * h + 0) * NK + i] = make_float2(m0, c0 * il);
        o2[(4 * h + 1) * NK + i] = make_float2(m1, c1 * il);
        o2[(4 * h + 2) * NK + i] = make_float2(m2, c2 * il);
        o2[(4 * h + 3) * NK + i] = make_float2(m3, c3 * il);
    }
}

__global__ __launch_bounds__(NT, 3)
void rocket_kernel(const float* __restrict__ x,     // (8,1,512)
                   const float* __restrict__ W,     // (10000,1,11)
                   const float* __restrict__ Bias,  // (10000,)
                   const int*   __restrict__ dil_,  // (10000,)
                   const int*   __restrict__ lo_,   // (10000,)
                   float*       __restrict__ out)   // (8, 20000) interleaved (max, ppv)
{
    extern __shared__ float xs[];   // swizzled [pos][8 batches], zero-padded
    const int tid = threadIdx.x;

    // zero fill
    float4* z4 = reinterpret_cast<float4*>(xs);
#pragma unroll
    for (int t = tid; t < XS_POS * 8 / 4; t += NT)
        z4[t] = make_float4(0.f, 0.f, 0.f, 0.f);
    __syncthreads();

    // transpose-load x with swizzle: logical xs[(s+512)*8 + b]
    for (int t = tid; t < 8 * SEQ; t += NT) {
        int b = t >> 9;
        int s = t & 511;
        int idx4 = (s + SEQ) * 2 + (b >> 2);
        int ph = idx4 ^ ((idx4 >> 3) & 6);
        xs[ph * 4 + (b & 3)] = x[t];
    }
    __syncthreads();

    const int lane = tid & 31;
    const int c = lane >> 1;
    const int h = lane & 1;
    const ulonglong2* xsu = reinterpret_cast<const ulonglong2*>(xs);

    while (true) {
        int i;
        if (lane == 0) i = atomicAdd(&g_ctr, 1);
        i = __shfl_sync(0xffffffffu, i, 0);
        if (i >= NK) break;

        float w[11];
        const float* wr = W + i * 11;
#pragma unroll
        for (int j = 0; j < 11; ++j) w[j] = __ldg(wr + j);
        const float bias = __ldg(Bias + i);
        const int   dil  = __ldg(dil_ + i);
        const int   lo   = __ldg(lo_ + i);

        // recover tap count from exact-zero weight tail
        if (w[7] == 0.f && w[8] == 0.f)
            process_i<7>(xsu, i, c, h, w, bias, dil, lo, out);
        else if (w[9] == 0.f && w[10] == 0.f)
            process_i<9>(xsu, i, c, h, w, bias, dil, lo, out);
        else
            process_i<11>(xsu, i, c, h, w, bias, dil, lo, out);
    }
}

extern "C" void kernel_launch(void* const* d_in, const int* in_sizes, int n_in,
                              void* d_out, int out_size) {
    const float* x    = (const float*)d_in[0];  // (8,1,512)
    const float* Wt   = (const float*)d_in[1];  // (10000,1,11)
    const float* Bias = (const float*)d_in[2];  // (10000,)
    // d_in[3] = base (unused: pad recovered from lo/dil/k)
    const int*   dil  = (const int*)d_in[4];
    const int*   lo   = (const int*)d_in[5];
    float* out = (float*)d_out;                 // (8, 20000)

    cudaFuncSetAttribute(rocket_kernel,
                         cudaFuncAttributeMaxDynamicSharedMemorySize, SMEM_BYTES);
    reset_ctr_kernel<<<1, 1>>>();
    rocket_kernel<<<NBLK, NT, SMEM_BYTES>>>(x, Wt, Bias, dil, lo, out);
}

// round 5
// speedup vs baseline: 1.6250x; 1.0608x over previous
#include <cuda_runtime.h>
#include <math.h>

#define NK     10000
#define SEQ    512
#define XS_POS 1792                      // positions: index = s + 512; worst read = 1023+pad+(M-1)d <= 1791
#define SMEM_BYTES (XS_POS * 8 * 4)      // 57344 B dynamic shared
#define NT     256
#define NBLK   592                       // 4 CTAs/SM * 148 SMs target

typedef unsigned long long ull;

__device__ int g_ctr;
__global__ void reset_ctr_kernel() { g_ctr = 0; }

static __device__ __forceinline__ ull pack2(float a, float b) {
    ull r; asm("mov.b64 %0, {%1, %2};" : "=l"(r) : "f"(a), "f"(b)); return r;
}
static __device__ __forceinline__ void unpack2(ull v, float& a, float& b) {
    asm("mov.b64 {%0, %1}, %2;" : "=f"(a), "=f"(b) : "l"(v));
}
static __device__ __forceinline__ ull fma2(ull a, ull b, ull c) {
    ull r; asm("fma.rn.f32x2 %0, %1, %2, %3;" : "=l"(r) : "l"(a), "l"(b), "l"(c)); return r;
}

// Process rocket conv-kernel i with compile-time tap count K and tile height M.
// Lane layout: c = lane>>1 (16 tile-lanes), h = lane&1 (batch half).
// Tile = M chain-consecutive outputs t0, t0+d, ..., t0+(M-1)d sharing K+M-1 loads.
// Accumulates s' = -s: max_t s = -min_t s'; ppv count = #(s' < 0) via sign bits.
// SAFETY: caller guarantees pad + (M-1)*dil <= 768 so all loads hit < XS_POS.
template<int K, int M>
static __device__ __forceinline__ void process_i(
    const ulonglong2* __restrict__ xsu, int i, int c, int h,
    const float* __restrict__ w, float bias, int dil, int lo, int pad,
    float* __restrict__ out)
{
    ull wn[K];
#pragma unroll
    for (int j = 0; j < K; ++j) wn[j] = pack2(-w[j], -w[j]);
    const ull biasn = pack2(-bias, -bias);

    const int dM = dil * M;
    const int stripes = (lo + dM - 1) / dM;            // once per i, warp-uniform
    const int ntiles = stripes * dil;
    const float inv_d = 1.0f / (float)dil;
    const int inc = dil * 2;                           // ulonglong2-index step per tap
    const int base0 = (SEQ - pad) * 2 + h;

    float mn0 = INFINITY, mn1 = INFINITY, mn2 = INFINITY, mn3 = INFINITY;
    unsigned cn0 = 0u, cn1 = 0u, cn2 = 0u, cn3 = 0u;

    for (int j = c; j < ntiles; j += 16) {
        // (stripe, off) = (j / dil, j % dil) via float reciprocal + correction
        int stripe = __float2int_rd(__int2float_rn(j) * inv_d);
        int off = j - stripe * dil;
        if (off < 0)         { --stripe; off += dil; }
        else if (off >= dil) { ++stripe; off -= dil; }
        const int t0 = stripe * dM + off;
        if (t0 >= lo) continue;

        int idx = base0 + t0 * 2;
        ull aL[M], aH[M];
#pragma unroll
        for (int q = 0; q < M; ++q) { aL[q] = biasn; aH[q] = biasn; }

#pragma unroll
        for (int v = 0; v < K + M - 1; ++v) {
            const int ph = idx ^ ((idx >> 3) & 6);     // bank swizzle within 128B row
            const ulonglong2 L = xsu[ph];
#pragma unroll
            for (int q = 0; q < M; ++q) {
                const int jj = v - q;
                if (jj >= 0 && jj < K) {
                    aL[q] = fma2(wn[jj], L.x, aL[q]);
                    aH[q] = fma2(wn[jj], L.y, aH[q]);
                }
            }
            idx += inc;
        }

#pragma unroll
        for (int q = 0; q < M; ++q) {
            if (t0 + q * dil < lo) {
                float s0, s1, s2, s3;
                unpack2(aL[q], s0, s1);
                unpack2(aH[q], s2, s3);
                mn0 = fminf(mn0, s0);  cn0 += __float_as_uint(s0) >> 31;
                mn1 = fminf(mn1, s1);  cn1 += __float_as_uint(s1) >> 31;
                mn2 = fminf(mn2, s2);  cn2 += __float_as_uint(s2) >> 31;
                mn3 = fminf(mn3, s3);  cn3 += __float_as_uint(s3) >> 31;
            }
        }
    }

    // reduce across the 16 tile-lanes (xor offsets 2..16 keep h fixed)
#pragma unroll
    for (int off = 2; off < 32; off <<= 1) {
        mn0 = fminf(mn0, __shfl_xor_sync(0xffffffffu, mn0, off));
        mn1 = fminf(mn1, __shfl_xor_sync(0xffffffffu, mn1, off));
        mn2 = fminf(mn2, __shfl_xor_sync(0xffffffffu, mn2, off));
        mn3 = fminf(mn3, __shfl_xor_sync(0xffffffffu, mn3, off));
        cn0 += __shfl_xor_sync(0xffffffffu, cn0, off);
        cn1 += __shfl_xor_sync(0xffffffffu, cn1, off);
        cn2 += __shfl_xor_sync(0xffffffffu, cn2, off);
        cn3 += __shfl_xor_sync(0xffffffffu, cn3, off);
    }

    if (c == 0) {
        const float il = 1.f / (float)lo;
        float2* o2 = reinterpret_cast<float2*>(out);
        o2[(4 * h + 0) * NK + i] = make_float2(-mn0, (float)cn0 * il);
        o2[(4 * h + 1) * NK + i] = make_float2(-mn1, (float)cn1 * il);
        o2[(4 * h + 2) * NK + i] = make_float2(-mn2, (float)cn2 * il);
        o2[(4 * h + 3) * NK + i] = make_float2(-mn3, (float)cn3 * il);
    }
}

__global__ __launch_bounds__(NT, 4)
void rocket_kernel(const float* __restrict__ x,     // (8,1,512)
                   const float* __restrict__ W,     // (10000,1,11)
                   const float* __restrict__ Bias,  // (10000,)
                   const int*   __restrict__ dil_,  // (10000,)
                   const int*   __restrict__ lo_,   // (10000,)
                   float*       __restrict__ out)   // (8, 20000) interleaved (max, ppv)
{
    extern __shared__ float xs[];   // swizzled [pos][8 batches], zero-padded
    const int tid = threadIdx.x;

    // zero fill
    float4* z4 = reinterpret_cast<float4*>(xs);
#pragma unroll
    for (int t = tid; t < XS_POS * 8 / 4; t += NT)
        z4[t] = make_float4(0.f, 0.f, 0.f, 0.f);
    __syncthreads();

    // transpose-load x with swizzle: logical xs[(s+512)*8 + b]
    for (int t = tid; t < 8 * SEQ; t += NT) {
        int b = t >> 9;
        int s = t & 511;
        int idx4 = (s + SEQ) * 2 + (b >> 2);
        int ph = idx4 ^ ((idx4 >> 3) & 6);
        xs[ph * 4 + (b & 3)] = x[t];
    }
    __syncthreads();

    const int lane = tid & 31;
    const int c = lane >> 1;
    const int h = lane & 1;
    const ulonglong2* xsu = reinterpret_cast<const ulonglong2*>(xs);

    while (true) {
        int i;
        if (lane == 0) i = atomicAdd(&g_ctr, 1);
        i = __shfl_sync(0xffffffffu, i, 0);
        if (i >= NK) break;

        float w[11];
        const float* wr = W + i * 11;
#pragma unroll
        for (int j = 0; j < 11; ++j) w[j] = __ldg(wr + j);
        const float bias = __ldg(Bias + i);
        const int   dil  = __ldg(dil_ + i);
        const int   lo   = __ldg(lo_ + i);

        // recover tap count from exact-zero weight tail
        if (w[7] == 0.f && w[8] == 0.f) {
            const int pad = (lo - SEQ + dil * 6) >> 1;
            if (pad + 5 * dil <= 768)   // M=6 tile stays inside XS_POS
                process_i<7, 6>(xsu, i, c, h, w, bias, dil, lo, pad, out);
            else
                process_i<7, 4>(xsu, i, c, h, w, bias, dil, lo, pad, out);
        } else if (w[9] == 0.f && w[10] == 0.f) {
            const int pad = (lo - SEQ + dil * 8) >> 1;   // pad+4d <= 756 always
            process_i<9, 5>(xsu, i, c, h, w, bias, dil, lo, pad, out);
        } else {
            const int pad = (lo - SEQ + dil * 10) >> 1;  // pad+3d <= 663 always
            process_i<11, 4>(xsu, i, c, h, w, bias, dil, lo, pad, out);
        }
    }
}

extern "C" void kernel_launch(void* const* d_in, const int* in_sizes, int n_in,
                              void* d_out, int out_size) {
    const float* x    = (const float*)d_in[0];  // (8,1,512)
    const float* Wt   = (const float*)d_in[1];  // (10000,1,11)
    const float* Bias = (const float*)d_in[2];  // (10000,)
    // d_in[3] = base (unused: pad recovered from lo/dil/k)
    const int*   dil  = (const int*)d_in[4];
    const int*   lo   = (const int*)d_in[5];
    float* out = (float*)d_out;                 // (8, 20000)

    cudaFuncSetAttribute(rocket_kernel,
                         cudaFuncAttributeMaxDynamicSharedMemorySize, SMEM_BYTES);
    reset_ctr_kernel<<<1, 1>>>();
    rocket_kernel<<<NBLK, NT, SMEM_BYTES>>>(x, Wt, Bias, dil, lo, out);
}